// round 1
// baseline (speedup 1.0000x reference)
#include <cuda_runtime.h>
#include <cuda_bf16.h>
#include <math.h>

// Problem constants
#define BATCH 8192
#define DIN   1025
#define HID   1024
#define NACT  1026
#define NHEAD 513
#define KSEQ  32

// Scratch activations (allocation-free: __device__ globals)
__device__ float g_h0[(size_t)BATCH * HID];
__device__ float g_h1[(size_t)BATCH * HID];
__device__ float g_logits[(size_t)BATCH * NACT];

// ---------------------------------------------------------------------------
// SGEMM: C[M,N] = act(A[M,K] @ W[K,N] + bias[N]), row-major, fp32.
// 128x128 block, 16 K-slice, 8x8 per-thread register tile, 256 threads.
// M is always a multiple of 128 here; N and K may be ragged (guarded).
// ---------------------------------------------------------------------------
#define BM 128
#define BN 128
#define BK 16
#define TM 8
#define TN 8

template <bool RELU>
__global__ void __launch_bounds__(256)
sgemm_bias_act(const float* __restrict__ A, const float* __restrict__ W,
               const float* __restrict__ bias, float* __restrict__ C,
               int M, int N, int K)
{
    __shared__ float As[BK][BM + 4];  // +4 pad: breaks the 16-way STS conflict
    __shared__ float Bs[BK][BN];

    const int tid = threadIdx.x;
    const int bm = blockIdx.y * BM;
    const int bn = blockIdx.x * BN;

    const int tx = tid & 15;          // 0..15 -> column group
    const int ty = tid >> 4;          // 0..15 -> row group
    const int rowBase = ty * TM;
    const int colBase = tx * TN;

    float acc[TM][TN];
#pragma unroll
    for (int i = 0; i < TM; i++)
#pragma unroll
        for (int j = 0; j < TN; j++) acc[i][j] = 0.0f;

    const int kTiles = (K + BK - 1) / BK;
    for (int kt = 0; kt < kTiles; kt++) {
        const int k0 = kt * BK;

        // Load A tile: BM*BK = 2048 elems, 8 per thread.
        // idx -> (mm = idx/BK, kk = idx%BK): consecutive lanes sweep kk (coalesced
        // 64B row segments in gmem).
#pragma unroll
        for (int i = 0; i < 8; i++) {
            int idx = i * 256 + tid;
            int mm = idx >> 4;         // idx / 16
            int kk = idx & 15;
            int kg = k0 + kk;
            float v = 0.0f;
            if (kg < K) v = A[(size_t)(bm + mm) * K + kg];
            As[kk][mm] = v;
        }
        // Load B tile: BK*BN = 2048 elems, 8 per thread.
        // idx -> (kk = idx/BN, nn = idx%BN): fully coalesced, conflict-free STS.
#pragma unroll
        for (int i = 0; i < 8; i++) {
            int idx = i * 256 + tid;
            int kk = idx >> 7;         // idx / 128
            int nn = idx & 127;
            int kg = k0 + kk;
            int ng = bn + nn;
            float v = 0.0f;
            if (kg < K && ng < N) v = W[(size_t)kg * N + ng];
            Bs[kk][nn] = v;
        }
        __syncthreads();

#pragma unroll
        for (int kk = 0; kk < BK; kk++) {
            float a[TM], b[TN];
#pragma unroll
            for (int i = 0; i < TM; i++) a[i] = As[kk][rowBase + i];
#pragma unroll
            for (int j = 0; j < TN; j++) b[j] = Bs[kk][colBase + j];
#pragma unroll
            for (int i = 0; i < TM; i++)
#pragma unroll
                for (int j = 0; j < TN; j++)
                    acc[i][j] = fmaf(a[i], b[j], acc[i][j]);
        }
        __syncthreads();
    }

    // Epilogue: bias + optional ReLU, guard ragged N.
#pragma unroll
    for (int i = 0; i < TM; i++) {
        int r = bm + rowBase + i;
#pragma unroll
        for (int j = 0; j < TN; j++) {
            int c = bn + colBase + j;
            if (c < N) {
                float v = acc[i][j] + bias[c];
                if (RELU) v = fmaxf(v, 0.0f);
                C[(size_t)r * N + c] = v;
            }
        }
    }
}

// ---------------------------------------------------------------------------
// Sampler: incremental log-softmax-without-replacement.
// One block of 64 threads per batch row; warp 0 = head R (cols [0,513)),
// warp 1 = head S (cols [513,1026)).
//
// With fixed shift m0 = max over the head's logits:
//   S1 = sum_remaining exp(l - m0)
//   S2 = sum_remaining (l - m0) * exp(l - m0)
//   lp(i)    = (l_i - m0) - log S1
//   ent_step = log S1 - S2 / S1
//   removal: S1 -= exp(l_i - m0);  S2 -= (l_i - m0) * exp(l_i - m0)
// Matches the reference semantics: ent accumulates whenever t < seq_len;
// logp/removal only when idx >= 0.
// ---------------------------------------------------------------------------
__global__ void __launch_bounds__(64)
sampler_kernel(const float* __restrict__ logits,
               const int* __restrict__ idxR, const int* __restrict__ lenR,
               const int* __restrict__ idxS, const int* __restrict__ lenS,
               float* __restrict__ out)
{
    const int b = blockIdx.x;
    const int w = threadIdx.x >> 5;        // 0 = R head, 1 = S head
    const int lane = threadIdx.x & 31;

    const float* lrow = logits + (size_t)b * NACT + w * NHEAD;
    const int* sidx = (w == 0 ? idxR : idxS) + (size_t)b * KSEQ;
    const int slen = (w == 0 ? lenR : lenS)[b];

    // 1) warp max over 513 logits
    float m = -INFINITY;
    for (int i = lane; i < NHEAD; i += 32) m = fmaxf(m, lrow[i]);
#pragma unroll
    for (int off = 16; off > 0; off >>= 1)
        m = fmaxf(m, __shfl_xor_sync(0xFFFFFFFFu, m, off));

    // 2) warp S1, S2
    float S1 = 0.0f, S2 = 0.0f;
    for (int i = lane; i < NHEAD; i += 32) {
        float l = lrow[i] - m;
        float e = expf(l);
        S1 += e;
        S2 += l * e;
    }
#pragma unroll
    for (int off = 16; off > 0; off >>= 1) {
        S1 += __shfl_xor_sync(0xFFFFFFFFu, S1, off);
        S2 += __shfl_xor_sync(0xFFFFFFFFu, S2, off);
    }

    // 3) sequential K-step loop (lane 0 only)
    __shared__ float sh[4];
    if (lane == 0) {
        float logp = 0.0f, ent = 0.0f;
        for (int t = 0; t < slen; t++) {
            float lS1 = logf(S1);
            ent += lS1 - S2 / S1;
            int id = sidx[t];
            if (id >= 0) {
                float l = lrow[id] - m;
                logp += l - lS1;
                float e = expf(l);
                S1 -= e;
                S2 -= l * e;
            }
        }
        sh[w * 2 + 0] = logp;
        sh[w * 2 + 1] = ent;
    }
    __syncthreads();
    if (threadIdx.x == 0) {
        out[b]         = sh[0] + sh[2];   // logpR + logpS
        out[BATCH + b] = sh[1] + sh[3];   // entR + entS
    }
}

// ---------------------------------------------------------------------------
// Launch
// ---------------------------------------------------------------------------
extern "C" void kernel_launch(void* const* d_in, const int* in_sizes, int n_in,
                              void* d_out, int out_size)
{
    const float* state = (const float*)d_in[0];   // (8192, 1025)
    const float* W0    = (const float*)d_in[1];   // (1025, 1024)
    const float* b0    = (const float*)d_in[2];   // (1024,)
    const float* W1    = (const float*)d_in[3];   // (1024, 1024)
    const float* b1    = (const float*)d_in[4];   // (1024,)
    const float* W2    = (const float*)d_in[5];   // (1024, 1026)
    const float* b2    = (const float*)d_in[6];   // (1026,)
    const int* seq_idx_R = (const int*)d_in[7];   // (8192, 32)
    const int* seq_len_R = (const int*)d_in[8];   // (8192,)
    const int* seq_idx_S = (const int*)d_in[9];   // (8192, 32)
    const int* seq_len_S = (const int*)d_in[10];  // (8192,)
    float* out = (float*)d_out;                   // (2, 8192)

    float *h0, *h1, *lg;
    cudaGetSymbolAddress((void**)&h0, g_h0);
    cudaGetSymbolAddress((void**)&h1, g_h1);
    cudaGetSymbolAddress((void**)&lg, g_logits);

    dim3 blk(256);
    dim3 g1((HID + BN - 1) / BN, BATCH / BM);   // (8, 64)
    dim3 g3((NACT + BN - 1) / BN, BATCH / BM);  // (9, 64)

    sgemm_bias_act<true ><<<g1, blk>>>(state, W0, b0, h0, BATCH, HID, DIN);
    sgemm_bias_act<true ><<<g1, blk>>>(h0,    W1, b1, h1, BATCH, HID, HID);
    sgemm_bias_act<false><<<g3, blk>>>(h1,    W2, b2, lg, BATCH, NACT, HID);

    sampler_kernel<<<BATCH, 64>>>(lg, seq_idx_R, seq_len_R,
                                  seq_idx_S, seq_len_S, out);
}

// round 2
// speedup vs baseline: 3.6214x; 3.6214x over previous
#include <cuda_runtime.h>
#include <cuda_bf16.h>
#include <math.h>
#include <stdint.h>

// Problem constants
#define BATCH 8192
#define DIN   1025
#define HID   1024
#define NACT  1026
#define NHEAD 513
#define KSEQ  32

// Padded dims
#define DINP  1056   // DIN padded to mult of 32
#define NACTP 1152   // NACT padded to mult of 128

// ---------------------------------------------------------------------------
// Scratch (allocation-free: __device__ globals)
// ---------------------------------------------------------------------------
__device__ __nv_bfloat16 g_Shi[(size_t)BATCH * DINP];
__device__ __nv_bfloat16 g_Slo[(size_t)BATCH * DINP];
__device__ __nv_bfloat16 g_W0h[(size_t)DINP * HID];
__device__ __nv_bfloat16 g_W0l[(size_t)DINP * HID];
__device__ __nv_bfloat16 g_W1h[(size_t)HID * HID];
__device__ __nv_bfloat16 g_W1l[(size_t)HID * HID];
__device__ __nv_bfloat16 g_W2h[(size_t)HID * NACTP];
__device__ __nv_bfloat16 g_W2l[(size_t)HID * NACTP];
__device__ __nv_bfloat16 g_H0h[(size_t)BATCH * HID];
__device__ __nv_bfloat16 g_H0l[(size_t)BATCH * HID];
__device__ __nv_bfloat16 g_H1h[(size_t)BATCH * HID];
__device__ __nv_bfloat16 g_H1l[(size_t)BATCH * HID];
__device__ float g_logits[(size_t)BATCH * NACT];

// ---------------------------------------------------------------------------
// Split/pad: fp32 [R,C] -> bf16 hi/lo [Rpad, Cpad], zero outside [R,C].
// hi = bf16(x); lo = bf16(x - float(hi))  =>  hi+lo carries ~16 mantissa bits.
// ---------------------------------------------------------------------------
__global__ void split_pad_kernel(const float* __restrict__ src,
                                 __nv_bfloat16* __restrict__ hi,
                                 __nv_bfloat16* __restrict__ lo,
                                 int R, int C, int Rpad, int Cpad)
{
    size_t total = (size_t)Rpad * Cpad;
    for (size_t idx = (size_t)blockIdx.x * blockDim.x + threadIdx.x;
         idx < total; idx += (size_t)gridDim.x * blockDim.x) {
        int r = (int)(idx / Cpad);
        int c = (int)(idx % Cpad);
        float v = 0.0f;
        if (r < R && c < C) v = src[(size_t)r * C + c];
        __nv_bfloat16 h = __float2bfloat16(v);
        __nv_bfloat16 l = __float2bfloat16(v - __bfloat162float(h));
        hi[idx] = h;
        lo[idx] = l;
    }
}

// ---------------------------------------------------------------------------
// PTX helpers
// ---------------------------------------------------------------------------
__device__ __forceinline__ void ldsm_x4(uint32_t& r0, uint32_t& r1,
                                        uint32_t& r2, uint32_t& r3,
                                        const void* p)
{
    uint32_t a = (uint32_t)__cvta_generic_to_shared(p);
    asm volatile("ldmatrix.sync.aligned.m8n8.x4.shared.b16 {%0,%1,%2,%3}, [%4];"
                 : "=r"(r0), "=r"(r1), "=r"(r2), "=r"(r3) : "r"(a));
}

__device__ __forceinline__ void ldsm_x4_trans(uint32_t& r0, uint32_t& r1,
                                              uint32_t& r2, uint32_t& r3,
                                              const void* p)
{
    uint32_t a = (uint32_t)__cvta_generic_to_shared(p);
    asm volatile("ldmatrix.sync.aligned.m8n8.x4.trans.shared.b16 {%0,%1,%2,%3}, [%4];"
                 : "=r"(r0), "=r"(r1), "=r"(r2), "=r"(r3) : "r"(a));
}

__device__ __forceinline__ void mma16816(float* d, const uint32_t* a, const uint32_t* b)
{
    asm volatile(
        "mma.sync.aligned.m16n8k16.row.col.f32.bf16.bf16.f32 "
        "{%0,%1,%2,%3}, {%4,%5,%6,%7}, {%8,%9}, {%0,%1,%2,%3};"
        : "+f"(d[0]), "+f"(d[1]), "+f"(d[2]), "+f"(d[3])
        : "r"(a[0]), "r"(a[1]), "r"(a[2]), "r"(a[3]),
          "r"(b[0]), "r"(b[1]));
}

// ---------------------------------------------------------------------------
// bf16-split tensor-core GEMM.
//   C[M,N] = act( (Ahi+Alo)[M,K] @ (Bhi+Blo)[K,N] + bias ), products lo*lo dropped.
// Block: 128x128 tile, BK=32, 256 threads = 8 warps in 2x4, warp tile 64x32.
// K is pre-padded to a multiple of 32 with zeros (no guards).
// OUT=0: relu, write bf16 hi/lo pair.  OUT=1: no act, write fp32, guard n<Nvalid.
// ---------------------------------------------------------------------------
#define GBM 128
#define GBN 128
#define GBK 32
#define APAD 40    // A smem row stride (halves): 80B rows -> conflict-free LDSM
#define BPAD 136   // B smem row stride (halves): 272B rows -> conflict-free LDSM

template <int OUT>
__global__ void __launch_bounds__(256)
gemm_bf16_split(const __nv_bfloat16* __restrict__ Ahi,
                const __nv_bfloat16* __restrict__ Alo, int lda,
                const __nv_bfloat16* __restrict__ Bhi,
                const __nv_bfloat16* __restrict__ Blo, int ldb,
                const float* __restrict__ bias,
                __nv_bfloat16* __restrict__ Chi,
                __nv_bfloat16* __restrict__ Clo,
                float* __restrict__ Cf, int ldc, int Nvalid,
                int kIters)
{
    __shared__ __nv_bfloat16 As[2][GBM][APAD];
    __shared__ __nv_bfloat16 Bs[2][GBK][BPAD];

    const int tid  = threadIdx.x;
    const int lane = tid & 31;
    const int wid  = tid >> 5;
    const int warpRow = (wid & 1) * 64;    // 2 warps along M
    const int warpCol = (wid >> 1) * 32;   // 4 warps along N
    const int bm = blockIdx.y * GBM;
    const int bn = blockIdx.x * GBN;

    float acc[4][4][4];   // [mi][nj][frag]
#pragma unroll
    for (int i = 0; i < 4; i++)
#pragma unroll
        for (int j = 0; j < 4; j++)
#pragma unroll
            for (int f = 0; f < 4; f++) acc[i][j][f] = 0.0f;

    // ldmatrix lane addressing precompute
    const int lm  = lane >> 3;     // which 8x8 matrix (0..3)
    const int lr  = lane & 7;      // row within matrix
    // A (non-trans): row = base + (lm&1)*8 + lr, col = ks + (lm>>1)*8
    const int aRowOff = (lm & 1) * 8 + lr;
    const int aColOff = (lm >> 1) * 8;
    // B (trans): krow = ks + (lm&1)*8 + lr, col = base + (lm>>1)*8
    const int bRowOff = (lm & 1) * 8 + lr;
    const int bColOff = (lm >> 1) * 8;

    for (int kt = 0; kt < kIters; kt++) {
        const int k0 = kt * GBK;

        // Load A tiles (hi+lo): 128 rows x 32 halves each, uint2 (4 halves) per ld
#pragma unroll
        for (int i = 0; i < 4; i++) {
            int idx = i * 256 + tid;
            int r  = idx >> 3;
            int kk = (idx & 7) << 2;
            *(uint2*)&As[0][r][kk] = *(const uint2*)&Ahi[(size_t)(bm + r) * lda + k0 + kk];
            *(uint2*)&As[1][r][kk] = *(const uint2*)&Alo[(size_t)(bm + r) * lda + k0 + kk];
        }
        // Load B tiles (hi+lo): 32 rows x 128 halves each
#pragma unroll
        for (int i = 0; i < 4; i++) {
            int idx = i * 256 + tid;
            int r  = idx >> 5;
            int nn = (idx & 31) << 2;
            *(uint2*)&Bs[0][r][nn] = *(const uint2*)&Bhi[(size_t)(k0 + r) * ldb + bn + nn];
            *(uint2*)&Bs[1][r][nn] = *(const uint2*)&Blo[(size_t)(k0 + r) * ldb + bn + nn];
        }
        __syncthreads();

#pragma unroll
        for (int ks = 0; ks < GBK; ks += 16) {
            uint32_t ahi[4][4], alo[4][4], bhi[4][2], blo[4][2];
            // A fragments: 4 m-tiles of 16 rows
#pragma unroll
            for (int mi = 0; mi < 4; mi++) {
                int row = warpRow + mi * 16 + aRowOff;
                int col = ks + aColOff;
                ldsm_x4(ahi[mi][0], ahi[mi][1], ahi[mi][2], ahi[mi][3], &As[0][row][col]);
                ldsm_x4(alo[mi][0], alo[mi][1], alo[mi][2], alo[mi][3], &As[1][row][col]);
            }
            // B fragments: 2 x4.trans loads cover 16 cols each -> 4 n-frags of 8
#pragma unroll
            for (int ni = 0; ni < 2; ni++) {
                int krow = ks + bRowOff;
                int col  = warpCol + ni * 16 + bColOff;
                uint32_t r0, r1, r2, r3;
                ldsm_x4_trans(r0, r1, r2, r3, &Bs[0][krow][col]);
                bhi[ni * 2 + 0][0] = r0; bhi[ni * 2 + 0][1] = r1;
                bhi[ni * 2 + 1][0] = r2; bhi[ni * 2 + 1][1] = r3;
                ldsm_x4_trans(r0, r1, r2, r3, &Bs[1][krow][col]);
                blo[ni * 2 + 0][0] = r0; blo[ni * 2 + 0][1] = r1;
                blo[ni * 2 + 1][0] = r2; blo[ni * 2 + 1][1] = r3;
            }
            // 3 split products into the same accumulators
#pragma unroll
            for (int mi = 0; mi < 4; mi++)
#pragma unroll
                for (int nj = 0; nj < 4; nj++) {
                    mma16816(acc[mi][nj], ahi[mi], bhi[nj]);
                    mma16816(acc[mi][nj], ahi[mi], blo[nj]);
                    mma16816(acc[mi][nj], alo[mi], bhi[nj]);
                }
        }
        __syncthreads();
    }

    // Epilogue. C frag mapping: lane -> groupID = lane>>2, tg = lane&3.
    //   c0,c1: (row=groupID,     col=tg*2, tg*2+1)
    //   c2,c3: (row=groupID + 8, col=tg*2, tg*2+1)
    const int gid = lane >> 2;
    const int tg  = lane & 3;
#pragma unroll
    for (int mi = 0; mi < 4; mi++) {
#pragma unroll
        for (int nj = 0; nj < 4; nj++) {
            int col = bn + warpCol + nj * 8 + tg * 2;
            float bv0 = 0.0f, bv1 = 0.0f;
            if (OUT == 0 || col + 1 < Nvalid) {  // pairs never straddle Nvalid (even)
                bv0 = bias[col];
                bv1 = bias[col + 1];
            }
#pragma unroll
            for (int half = 0; half < 2; half++) {
                int row = bm + warpRow + mi * 16 + gid + half * 8;
                float v0 = acc[mi][nj][half * 2 + 0] + bv0;
                float v1 = acc[mi][nj][half * 2 + 1] + bv1;
                if (OUT == 0) {
                    v0 = fmaxf(v0, 0.0f);
                    v1 = fmaxf(v1, 0.0f);
                    __nv_bfloat16 h0 = __float2bfloat16(v0);
                    __nv_bfloat16 h1 = __float2bfloat16(v1);
                    __nv_bfloat16 l0 = __float2bfloat16(v0 - __bfloat162float(h0));
                    __nv_bfloat16 l1 = __float2bfloat16(v1 - __bfloat162float(h1));
                    __nv_bfloat162 hp; hp.x = h0; hp.y = h1;
                    __nv_bfloat162 lp; lp.x = l0; lp.y = l1;
                    *(__nv_bfloat162*)&Chi[(size_t)row * ldc + col] = hp;
                    *(__nv_bfloat162*)&Clo[(size_t)row * ldc + col] = lp;
                } else {
                    if (col + 1 < Nvalid) {
                        float2 v; v.x = v0; v.y = v1;
                        *(float2*)&Cf[(size_t)row * ldc + col] = v;
                    }
                }
            }
        }
    }
}

// ---------------------------------------------------------------------------
// Sampler: incremental log-softmax-without-replacement (O(N) + O(K) per head).
// ---------------------------------------------------------------------------
__global__ void __launch_bounds__(64)
sampler_kernel(const float* __restrict__ logits,
               const int* __restrict__ idxR, const int* __restrict__ lenR,
               const int* __restrict__ idxS, const int* __restrict__ lenS,
               float* __restrict__ out)
{
    const int b = blockIdx.x;
    const int w = threadIdx.x >> 5;
    const int lane = threadIdx.x & 31;

    const float* lrow = logits + (size_t)b * NACT + w * NHEAD;
    const int* sidx = (w == 0 ? idxR : idxS) + (size_t)b * KSEQ;
    const int slen = (w == 0 ? lenR : lenS)[b];

    float m = -INFINITY;
    for (int i = lane; i < NHEAD; i += 32) m = fmaxf(m, lrow[i]);
#pragma unroll
    for (int off = 16; off > 0; off >>= 1)
        m = fmaxf(m, __shfl_xor_sync(0xFFFFFFFFu, m, off));

    float S1 = 0.0f, S2 = 0.0f;
    for (int i = lane; i < NHEAD; i += 32) {
        float l = lrow[i] - m;
        float e = expf(l);
        S1 += e;
        S2 += l * e;
    }
#pragma unroll
    for (int off = 16; off > 0; off >>= 1) {
        S1 += __shfl_xor_sync(0xFFFFFFFFu, S1, off);
        S2 += __shfl_xor_sync(0xFFFFFFFFu, S2, off);
    }

    __shared__ float sh[4];
    if (lane == 0) {
        float logp = 0.0f, ent = 0.0f;
        for (int t = 0; t < slen; t++) {
            float lS1 = logf(S1);
            ent += lS1 - S2 / S1;
            int id = sidx[t];
            if (id >= 0) {
                float l = lrow[id] - m;
                logp += l - lS1;
                float e = expf(l);
                S1 -= e;
                S2 -= l * e;
            }
        }
        sh[w * 2 + 0] = logp;
        sh[w * 2 + 1] = ent;
    }
    __syncthreads();
    if (threadIdx.x == 0) {
        out[b]         = sh[0] + sh[2];
        out[BATCH + b] = sh[1] + sh[3];
    }
}

// ---------------------------------------------------------------------------
// Launch
// ---------------------------------------------------------------------------
extern "C" void kernel_launch(void* const* d_in, const int* in_sizes, int n_in,
                              void* d_out, int out_size)
{
    const float* state = (const float*)d_in[0];
    const float* W0    = (const float*)d_in[1];
    const float* b0    = (const float*)d_in[2];
    const float* W1    = (const float*)d_in[3];
    const float* b1    = (const float*)d_in[4];
    const float* W2    = (const float*)d_in[5];
    const float* b2    = (const float*)d_in[6];
    const int* seq_idx_R = (const int*)d_in[7];
    const int* seq_len_R = (const int*)d_in[8];
    const int* seq_idx_S = (const int*)d_in[9];
    const int* seq_len_S = (const int*)d_in[10];
    float* out = (float*)d_out;

    __nv_bfloat16 *Shi, *Slo, *W0h, *W0l, *W1h, *W1l, *W2h, *W2l;
    __nv_bfloat16 *H0h, *H0l, *H1h, *H1l;
    float* lg;
    cudaGetSymbolAddress((void**)&Shi, g_Shi);
    cudaGetSymbolAddress((void**)&Slo, g_Slo);
    cudaGetSymbolAddress((void**)&W0h, g_W0h);
    cudaGetSymbolAddress((void**)&W0l, g_W0l);
    cudaGetSymbolAddress((void**)&W1h, g_W1h);
    cudaGetSymbolAddress((void**)&W1l, g_W1l);
    cudaGetSymbolAddress((void**)&W2h, g_W2h);
    cudaGetSymbolAddress((void**)&W2l, g_W2l);
    cudaGetSymbolAddress((void**)&H0h, g_H0h);
    cudaGetSymbolAddress((void**)&H0l, g_H0l);
    cudaGetSymbolAddress((void**)&H1h, g_H1h);
    cudaGetSymbolAddress((void**)&H1l, g_H1l);
    cudaGetSymbolAddress((void**)&lg, g_logits);

    // Split + pad inputs/weights to bf16 hi/lo
    split_pad_kernel<<<2048, 256>>>(state, Shi, Slo, BATCH, DIN, BATCH, DINP);
    split_pad_kernel<<<1024, 256>>>(W0, W0h, W0l, DIN, HID, DINP, HID);
    split_pad_kernel<<<1024, 256>>>(W1, W1h, W1l, HID, HID, HID, HID);
    split_pad_kernel<<<1024, 256>>>(W2, W2h, W2l, HID, NACT, HID, NACTP);

    dim3 blk(256);
    dim3 g1(HID / GBN, BATCH / GBM);     // (8, 64)
    dim3 g3(NACTP / GBN, BATCH / GBM);   // (9, 64)

    gemm_bf16_split<0><<<g1, blk>>>(Shi, Slo, DINP, W0h, W0l, HID, b0,
                                    H0h, H0l, nullptr, HID, HID, DINP / GBK);
    gemm_bf16_split<0><<<g1, blk>>>(H0h, H0l, HID, W1h, W1l, HID, b1,
                                    H1h, H1l, nullptr, HID, HID, HID / GBK);
    gemm_bf16_split<1><<<g3, blk>>>(H1h, H1l, HID, W2h, W2l, NACTP, b2,
                                    nullptr, nullptr, lg, NACT, NACT, HID / GBK);

    sampler_kernel<<<BATCH, 64>>>(lg, seq_idx_R, seq_len_R,
                                  seq_idx_S, seq_len_S, out);
}